// round 4
// baseline (speedup 1.0000x reference)
#include <cuda_runtime.h>

#define FULLM 0xffffffffu
#define B_N 1024
#define L_N 1024
#define T_N 21

__device__ double g_sum;
__device__ double g_cnt;

__global__ void init_k() { g_sum = 0.0; g_cnt = 0.0; }

__device__ __forceinline__ unsigned long long pk2(float lo, float hi) {
    unsigned long long r;
    asm("mov.b64 %0, {%1, %2};" : "=l"(r) : "f"(lo), "f"(hi));
    return r;
}
__device__ __forceinline__ void fma2(unsigned long long& acc, unsigned long long a, unsigned long long b) {
    asm("fma.rn.f32x2 %0, %1, %2, %0;" : "+l"(acc) : "l"(a), "l"(b));
}
__device__ __forceinline__ void unpk(unsigned long long v, float& lo, float& hi) {
    asm("mov.b64 {%0, %1}, %2;" : "=f"(lo), "=f"(hi) : "l"(v));
}

// 1 warp per block; 4 sequences per warp; 8 lanes per sequence.
// Lane l8 owns alpha[j] for j = l8, l8+8, l8+16 (j2 valid only for l8<5).
__global__ __launch_bounds__(32) void crf_k(
    const float* __restrict__ em, const int* __restrict__ tags,
    const int* __restrict__ mask,
    const float* __restrict__ startv, const float* __restrict__ endv,
    const float* __restrict__ transv)
{
    __shared__ float tr_sm[T_N * T_N];
    int tid = threadIdx.x;
    for (int i = tid; i < T_N * T_N; i += 32) tr_sm[i] = transv[i];
    __syncwarp();

    int lane = tid & 31;
    int l8 = lane & 7;
    int gb = lane & 24;                    // group base lane
    int seq = blockIdx.x * 4 + (lane >> 3);

    int j0 = l8, j1 = l8 + 8, j2 = l8 + 16;
    bool p2ok = (l8 < 5);
    int j2c = p2ok ? j2 : 20;              // clamped for address safety only

    // E columns for this lane's three outputs, source-packed in pairs.
    unsigned long long ep0[10], ep1[10], ep2[10];
    float e0s, e1s, e2s;
    {
        float c0[21], c1[21], c2[21];
        #pragma unroll
        for (int s = 0; s < T_N; s++) {
            c0[s] = __expf(__ldg(transv + s * T_N + j0));
            c1[s] = __expf(__ldg(transv + s * T_N + j1));
            c2[s] = p2ok ? __expf(__ldg(transv + s * T_N + j2)) : 0.f;
        }
        #pragma unroll
        for (int m = 0; m < 10; m++) {
            ep0[m] = pk2(c0[2*m], c0[2*m+1]);
            ep1[m] = pk2(c1[2*m], c1[2*m+1]);
            ep2[m] = pk2(c2[2*m], c2[2*m+1]);
        }
        e0s = c0[20]; e1s = c1[20]; e2s = c2[20];
    }

    const float* pe = em + (size_t)seq * (L_N * T_N);
    const int* tgl = tags + (size_t)seq * L_N + l8;   // lane-offset tag stream
    const int* mkl = mask + (size_t)seq * L_N + l8;

    // ---- t = 0 ----
    float r00 = __ldg(pe + j0);
    float r01 = __ldg(pe + j1);
    float r02 = p2ok ? __ldg(pe + j2) : 0.f;
    float a0 = __expf(__ldg(startv + j0) + r00);
    float a1 = __expf(__ldg(startv + j1) + r01);
    float a2 = p2ok ? __expf(__ldg(startv + j2) + r02) : 0.f;
    float logZ = 0.f;

    // tag/mask chunks of 8 steps, one chunk prefetched ahead
    int tagc = __ldg(tgl);
    int mc   = __ldg(mkl) ? 1 : 0;
    int tagn = __ldg(tgl + 8);
    int mn   = __ldg(mkl + 8) ? 1 : 0;

    int tg0 = __shfl_sync(FULLM, tagc, gb);
    int m0  = __shfl_sync(FULLM, mc, gb);
    float g0 = __shfl_sync(FULLM, r00, gb + (tg0 & 7));
    float g1 = __shfl_sync(FULLM, r01, gb + (tg0 & 7));
    float g2 = __shfl_sync(FULLM, r02, gb + (tg0 & 7));
    float emt0 = tg0 < 8 ? g0 : (tg0 < 16 ? g1 : g2);
    float score = __ldg(startv + tg0) + emt0;
    int prev = tg0;
    int cnt = m0;

    // emission software pipeline, depth 4
    float b0[4], b1[4], b2[4];
    #pragma unroll
    for (int k = 0; k < 4; k++) {
        size_t off = (size_t)(1 + k) * T_N;
        b0[k] = __ldg(pe + off + j0);
        b1[k] = __ldg(pe + off + j1);
        b2[k] = __ldg(pe + off + j2c);
    }

    #pragma unroll 4
    for (int t = 1; t < L_N; t++) {
        if ((t & 7) == 0) {
            tagc = tagn; mc = mn;
            int nt = t + 8;
            if (nt < L_N) {
                tagn = __ldg(tgl + nt);
                mn   = __ldg(mkl + nt) ? 1 : 0;
            }
        }
        int slot = (t - 1) & 3;
        float cur0 = b0[slot], cur1 = b1[slot], cur2 = b2[slot];
        int tp = t + 4;
        if (tp < L_N) {
            size_t off = (size_t)tp * T_N;
            b0[slot] = __ldg(pe + off + j0);
            b1[slot] = __ldg(pe + off + j1);
            b2[slot] = __ldg(pe + off + j2c);
        }

        float p0 = __expf(cur0);
        float p1 = __expf(cur1);
        float p2 = __expf(cur2);

        // broadcast 21 alpha values to the whole 8-lane group (serves all 4 groups at once)
        float vs[21];
        #pragma unroll
        for (int s = 0; s < 8; s++) vs[s]      = __shfl_sync(FULLM, a0, gb + s);
        #pragma unroll
        for (int s = 0; s < 8; s++) vs[8 + s]  = __shfl_sync(FULLM, a1, gb + s);
        #pragma unroll
        for (int s = 0; s < 5; s++) vs[16 + s] = __shfl_sync(FULLM, a2, gb + s);

        // packed mat-vec: 30 FFMA2 + 3 tail FFMA
        unsigned long long acc0 = 0ull, acc1 = 0ull, acc2 = 0ull;
        #pragma unroll
        for (int m = 0; m < 10; m++) {
            unsigned long long P = pk2(vs[2*m], vs[2*m+1]);
            fma2(acc0, P, ep0[m]);
            fma2(acc1, P, ep1[m]);
            fma2(acc2, P, ep2[m]);
        }
        float x0, y0, x1, y1, x2, y2;
        unpk(acc0, x0, y0); unpk(acc1, x1, y1); unpk(acc2, x2, y2);
        float n0 = fmaf(vs[20], e0s, x0 + y0) * p0;
        float n1 = fmaf(vs[20], e1s, x1 + y1) * p1;
        float n2 = fmaf(vs[20], e2s, x2 + y2) * p2;

        // numerator
        int ct = __shfl_sync(FULLM, tagc, gb + (t & 7));
        int m  = __shfl_sync(FULLM, mc,   gb + (t & 7));
        float s0 = __shfl_sync(FULLM, cur0, gb + (ct & 7));
        float s1 = __shfl_sync(FULLM, cur1, gb + (ct & 7));
        float s2 = __shfl_sync(FULLM, cur2, gb + (ct & 7));
        float emt = ct < 8 ? s0 : (ct < 16 ? s1 : s2);
        if (m) {
            score += tr_sm[prev * T_N + ct] + emt;
            cnt++;
            a0 = n0; a1 = n1; a2 = n2;
        }
        prev = ct;

        // renormalize by alpha[0] (lives in lane gb, reg a0) every 4 steps
        if ((t & 3) == 0) {
            float d = __shfl_sync(FULLM, a0, gb);
            float inv = __fdividef(1.f, d);
            a0 *= inv; a1 *= inv; a2 *= inv;
            logZ += __logf(d);
        }
    }

    // denominator
    float X0 = __expf(__ldg(endv + j0));
    float X1 = __expf(__ldg(endv + j1));
    float X2 = p2ok ? __expf(__ldg(endv + j2)) : 0.f;
    float v = a0 * X0 + a1 * X1 + a2 * X2;
    v += __shfl_xor_sync(FULLM, v, 1);
    v += __shfl_xor_sync(FULLM, v, 2);
    v += __shfl_xor_sync(FULLM, v, 4);
    float denom = logZ + __logf(v);

    if (l8 == 0) {
        int li = cnt > 0 ? cnt - 1 : 0;
        int lt = __ldg(tags + (size_t)seq * L_N + li);
        float sc = score + __ldg(endv + lt);
        atomicAdd(&g_sum, (double)(sc - denom));
        atomicAdd(&g_cnt, (double)cnt);
    }
}

__global__ void fin_k(float* out) { out[0] = (float)(g_sum / g_cnt); }

extern "C" void kernel_launch(void* const* d_in, const int* in_sizes, int n_in,
                              void* d_out, int out_size) {
    const float* em     = (const float*)d_in[0];
    const int* tags     = (const int*)d_in[1];
    const int* mask     = (const int*)d_in[2];
    const float* startv = (const float*)d_in[3];
    const float* endv   = (const float*)d_in[4];
    const float* trans  = (const float*)d_in[5];

    init_k<<<1, 1>>>();
    crf_k<<<B_N / 4, 32>>>(em, tags, mask, startv, endv, trans);
    fin_k<<<1, 1>>>((float*)d_out);
}

// round 5
// speedup vs baseline: 1.3325x; 1.3325x over previous
#include <cuda_runtime.h>

#define FULLM 0xffffffffu
#define B_N 1024
#define L_N 1024
#define T_N 21

__device__ double g_sum;
__device__ double g_cnt;

__global__ void init_k() { g_sum = 0.0; g_cnt = 0.0; }

typedef unsigned long long ull;

__device__ __forceinline__ ull pk2(float lo, float hi) {
    ull r; asm("mov.b64 %0, {%1, %2};" : "=l"(r) : "f"(lo), "f"(hi)); return r;
}
__device__ __forceinline__ void fma2(ull& a, ull x, ull y) {
    asm("fma.rn.f32x2 %0, %1, %2, %0;" : "+l"(a) : "l"(x), "l"(y));
}
__device__ __forceinline__ ull add2(ull x, ull y) {
    ull r; asm("add.rn.f32x2 %0, %1, %2;" : "=l"(r) : "l"(x), "l"(y)); return r;
}
__device__ __forceinline__ void unpk(ull v, float& lo, float& hi) {
    asm("mov.b64 {%0, %1}, %2;" : "=f"(lo), "=f"(hi) : "l"(v));
}

// One 32-thread block per sequence. Lane j owns alpha[j] (j<21).
// Broadcast of alpha via double-buffered smem: 1 STS + bar(3cyc) + 6 LDS.128.
__global__ __launch_bounds__(32) void crf_k(
    const float* __restrict__ em, const int* __restrict__ tags,
    const int* __restrict__ mask,
    const float* __restrict__ startv, const float* __restrict__ endv,
    const float* __restrict__ transv)
{
    __shared__ float4 abuf[2][6];   // [parity][24 floats]
    int lane = threadIdx.x;
    int seq = blockIdx.x;
    bool act = lane < T_N;
    int j = act ? lane : (T_N - 1);

    // E columns packed as 12 f32x2 pairs (rows 21..23 are zero).
    ull ep[12];
    {
        float c[24];
        #pragma unroll
        for (int s = 0; s < 24; s++)
            c[s] = (s < T_N && act) ? __expf(__ldg(transv + s * T_N + lane)) : 0.f;
        #pragma unroll
        for (int m = 0; m < 12; m++) ep[m] = pk2(c[2*m], c[2*m+1]);
    }

    const float* pe = em + (size_t)seq * (L_N * T_N);
    const int* tg = tags + (size_t)seq * L_N;
    const int* mk = mask + (size_t)seq * L_N;

    // zero the pad entries (21..23) of both buffers, written once
    if (lane >= T_N && lane < 24) {
        ((float*)abuf[0])[lane] = 0.f;
        ((float*)abuf[1])[lane] = 0.f;
    }

    // ---- t = 0 ----
    float em0 = __ldg(pe + j);
    float newv = act ? __expf(__ldg(startv + j) + em0) : 0.f;
    if (act) ((float*)abuf[0])[lane] = newv;
    __syncthreads();

    float logZ = 0.f;
    int tg0 = __ldg(tg);
    float score = __ldg(startv + tg0) + __ldg(pe + tg0);
    int cnt = __ldg(mk) ? 1 : 0;
    int prev = tg0;

    // emission software pipeline, depth 8 (rows 1..8)
    float ebuf[8];
    #pragma unroll
    for (int k = 0; k < 8; k++) ebuf[k] = __ldg(pe + (size_t)(1 + k) * T_N + j);

    float inv = 1.f, lg = 0.f;

    auto STEP = [&](int t, int ct, int m, bool do_renorm, bool prep_renorm) {
        float cur = ebuf[(t - 1) & 7];
        if (t + 8 < L_N) ebuf[(t - 1) & 7] = __ldg(pe + (size_t)(t + 8) * T_N + j);
        float p = __expf(cur);

        const float4* rb = abuf[(t - 1) & 1];
        float4 v0 = rb[0], v1 = rb[1], v2 = rb[2];
        float4 v3 = rb[3], v4 = rb[4], v5 = rb[5];

        if (prep_renorm) { inv = __fdividef(1.f, v0.x); lg = __logf(v0.x); }

        ull a0 = 0ull, a1 = 0ull, a2 = 0ull;
        fma2(a0, pk2(v0.x, v0.y), ep[0]);  fma2(a1, pk2(v0.z, v0.w), ep[1]);
        fma2(a2, pk2(v1.x, v1.y), ep[2]);  fma2(a0, pk2(v1.z, v1.w), ep[3]);
        fma2(a1, pk2(v2.x, v2.y), ep[4]);  fma2(a2, pk2(v2.z, v2.w), ep[5]);
        fma2(a0, pk2(v3.x, v3.y), ep[6]);  fma2(a1, pk2(v3.z, v3.w), ep[7]);
        fma2(a2, pk2(v4.x, v4.y), ep[8]);  fma2(a0, pk2(v4.z, v4.w), ep[9]);
        fma2(a1, pk2(v5.x, v5.y), ep[10]); fma2(a2, pk2(v5.z, v5.w), ep[11]);
        ull at = add2(add2(a0, a1), a2);
        float lo, hi; unpk(at, lo, hi);
        float nxt = (lo + hi) * p;

        // numerator (uniform across warp; L1-hit broadcast loads)
        float ltr = __ldg(transv + prev * T_N + ct);
        float emt = __ldg(pe + (size_t)t * T_N + ct);
        if (m) { score += ltr + emt; cnt++; }

        float out = m ? nxt : newv;
        if (do_renorm) { out *= inv; logZ += lg; }
        newv = out;
        if (act) ((float*)abuf[t & 1])[lane] = out;
        __syncthreads();
        prev = ct;
    };

    {   // chunk 0: steps 1..3
        int4 tc = __ldg((const int4*)tg);
        int4 mc = __ldg((const int4*)mk);
        STEP(1, tc.y, mc.y, false, false);
        STEP(2, tc.z, mc.z, false, false);
        STEP(3, tc.w, mc.w, false, true);
    }
    for (int c4 = 1; c4 < L_N / 4; c4++) {
        int4 tc = __ldg((const int4*)(tg + 4 * c4));
        int4 mc = __ldg((const int4*)(mk + 4 * c4));
        int tb = 4 * c4;
        STEP(tb + 0, tc.x, mc.x, true,  false);
        STEP(tb + 1, tc.y, mc.y, false, false);
        STEP(tb + 2, tc.z, mc.z, false, false);
        STEP(tb + 3, tc.w, mc.w, false, true);
    }

    // denominator: v = sum_j alpha_j * exp(end_j)   (alpha scaled; logZ holds the rest)
    float v = act ? newv * __expf(__ldg(endv + j)) : 0.f;
    #pragma unroll
    for (int off = 16; off > 0; off >>= 1) v += __shfl_xor_sync(FULLM, v, off);
    float denom = logZ + __logf(v);

    int li = cnt > 0 ? cnt - 1 : 0;
    score += __ldg(endv + __ldg(tg + li));

    if (lane == 0) {
        atomicAdd(&g_sum, (double)(score - denom));
        atomicAdd(&g_cnt, (double)cnt);
    }
}

__global__ void fin_k(float* out) { out[0] = (float)(g_sum / g_cnt); }

extern "C" void kernel_launch(void* const* d_in, const int* in_sizes, int n_in,
                              void* d_out, int out_size) {
    const float* em     = (const float*)d_in[0];
    const int* tags     = (const int*)d_in[1];
    const int* mask     = (const int*)d_in[2];
    const float* startv = (const float*)d_in[3];
    const float* endv   = (const float*)d_in[4];
    const float* trans  = (const float*)d_in[5];

    init_k<<<1, 1>>>();
    crf_k<<<B_N, 32>>>(em, tags, mask, startv, endv, trans);
    fin_k<<<1, 1>>>((float*)d_out);
}